// round 14
// baseline (speedup 1.0000x reference)
#include <cuda_runtime.h>
#include <cuda_fp16.h>
#include <cstdint>

#define DI __device__ __forceinline__

// ---------------- problem constants ----------------
constexpr int B_   = 16;
constexpr int C_   = 384;
constexpr int H_   = 56;
constexpr int W_   = 56;
constexpr int HW   = H_ * W_;          // 3136
constexpr int M_   = B_ * HW;          // 50176 (pixels)
constexpr int K0   = 2 * C_;           // 768
constexpr int K2T  = K0 / 2;           // 384 packed k-pairs
constexpr int NOUT = 384;

// ---------------- device scratch ----------------
__device__ __align__(256) uint32_t g_Xp[(size_t)B_ * K2T * HW];   // 77 MB
__device__ __align__(256) __half   g_Wh[NOUT * K0];               // fp16 W [n][k]

// ---------------- PTX helpers ----------------
DI uint32_t smem_u32(const void* p) {
    uint32_t a;
    asm("{ .reg .u64 t; cvta.to.shared.u64 t, %1; cvt.u32.u64 %0, t; }"
        : "=r"(a) : "l"(p));
    return a;
}

#define CP_ASYNC16(smem, gptr) \
    asm volatile("cp.async.cg.shared.global [%0], [%1], 16;" :: "r"(smem), "l"(gptr))
#define CP_COMMIT() asm volatile("cp.async.commit_group;")
#define CP_WAIT1()  asm volatile("cp.async.wait_group 1;")
#define CP_WAIT0()  asm volatile("cp.async.wait_group 0;")

DI void ldsm_x4(uint32_t* r, uint32_t addr) {
    asm volatile("ldmatrix.sync.aligned.m8n8.x4.shared.b16 {%0,%1,%2,%3}, [%4];"
                 : "=r"(r[0]), "=r"(r[1]), "=r"(r[2]), "=r"(r[3]) : "r"(addr));
}

DI uint32_t lds_u32(uint32_t addr) {
    uint32_t v;
    asm volatile("ld.shared.b32 %0, [%1];" : "=r"(v) : "r"(addr));
    return v;
}

// D[16 n][8 m] += A[16 n][16 k](f16) * B[16 k][8 m](f16), f32 accum
DI void mma_f16(float* d, const uint32_t* a, uint32_t b0, uint32_t b1) {
    asm volatile(
        "mma.sync.aligned.m16n8k16.row.col.f32.f16.f16.f32 "
        "{%0,%1,%2,%3},{%4,%5,%6,%7},{%8,%9},{%0,%1,%2,%3};"
        : "+f"(d[0]), "+f"(d[1]), "+f"(d[2]), "+f"(d[3])
        : "r"(a[0]), "r"(a[1]), "r"(a[2]), "r"(a[3]), "r"(b0), "r"(b1));
}

DI uint32_t pack_h2(float a, float b) {
    __half2 h = __halves2half2(__float2half_rn(a), __float2half_rn(b));
    return *reinterpret_cast<uint32_t*>(&h);
}

DI __half2 u2h(uint32_t u) { return *reinterpret_cast<__half2*>(&u); }
DI uint32_t h2u(__half2 h) { return *reinterpret_cast<uint32_t*>(&h); }

// ---------------- kernel 1: xjpack + fused W conversion ----------------
constexpr int TSTR = 120;
constexpr int XJ_SMEM = 118 * TSTR * 4;             // 56640 B
constexpr int XJ_BLOCKS = B_ * (C_ / 2);            // 3072
constexpr int W_BLOCKS  = 24;
constexpr int W_ELEMS   = NOUT * K0;                // 294912

__global__ void __launch_bounds__(448, 3) xjpack_kernel(
    const float* __restrict__ x, const float* __restrict__ wsrc) {
    extern __shared__ uint32_t t[];

    if (blockIdx.x >= XJ_BLOCKS) {
        const int tid0 = (blockIdx.x - XJ_BLOCKS) * 448
                       + threadIdx.y * 64 + threadIdx.x;
        for (int i = tid0; i < W_ELEMS; i += W_BLOCKS * 448)
            g_Wh[i] = __float2half_rn(wsrc[i]);
        return;
    }

    const int c2 = blockIdx.x % (C_ / 2);
    const int b  = blockIdx.x / (C_ / 2);
    const float* src0 = x + ((size_t)b * C_ + 2 * c2    ) * HW;
    const float* src1 = x + ((size_t)b * C_ + 2 * c2 + 1) * HW;

    const int w  = threadIdx.x;                 // 0..63 (>=56 idle)
    const int ty = threadIdx.y;                 // 0..6
    const int hb = ty * 8;

    if (w < W_) {
#pragma unroll
        for (int j = 0; j < 8; j++)
            t[(31 + hb + j) * TSTR + 31 + w] =
                pack_h2(src0[(hb + j) * W_ + w], src1[(hb + j) * W_ + w]);
    }
    __syncthreads();

    if (w < W_) {
#pragma unroll
        for (int r = ty; r < 31; r += 7) {
            t[r * TSTR + 31 + w]        = t[(r + 56) * TSTR + 31 + w];
            t[(r + 87) * TSTR + 31 + w] = t[(r + 31) * TSTR + 31 + w];
        }
    }
    if (w < 31) {
#pragma unroll
        for (int r = 31 + ty; r < 87; r += 7) {
            t[r * TSTR + w]      = t[r * TSTR + w + 56];
            t[r * TSTR + 87 + w] = t[r * TSTR + 31 + w];
        }
    }
    __syncthreads();

    if (w >= W_) return;

    const uint32_t* bp = &t[(31 + hb) * TSTR + 31 + w];
    uint32_t* dx = g_Xp + ((size_t)b * K2T + c2)       * HW + hb * W_ + w;
    uint32_t* dj = g_Xp + ((size_t)b * K2T + 192 + c2) * HW + hb * W_ + w;

    const __half2 zero = __half2half2(__float2half(0.f));

#pragma unroll 2
    for (int j = 0; j < 8; j++) {
        const uint32_t* p = bp + j * TSTR;
        const uint32_t vw = p[0];
        const __half2 v = u2h(vw);

        __half2 m = __hmin2(u2h(p[-1 * TSTR]),  u2h(p[1 * TSTR]));
        m = __hmin2(m, __hmin2(u2h(p[-3 * TSTR]),  u2h(p[3 * TSTR])));
        m = __hmin2(m, __hmin2(u2h(p[-7 * TSTR]),  u2h(p[7 * TSTR])));
        m = __hmin2(m, __hmin2(u2h(p[-15 * TSTR]), u2h(p[15 * TSTR])));
        m = __hmin2(m, __hmin2(u2h(p[-31 * TSTR]), u2h(p[31 * TSTR])));
        m = __hmin2(m, __hmin2(u2h(p[-1]),  u2h(p[1])));
        m = __hmin2(m, __hmin2(u2h(p[-3]),  u2h(p[3])));
        m = __hmin2(m, __hmin2(u2h(p[-7]),  u2h(p[7])));
        m = __hmin2(m, __hmin2(u2h(p[-15]), u2h(p[15])));
        m = __hmin2(m, __hmin2(u2h(p[-31]), u2h(p[31])));

        dx[j * W_] = vw;
        dj[j * W_] = h2u(__hmax2(__hsub2(v, m), zero));
    }
}

// ---------------- kernel 2: fp16 mma.sync GEMM + BN + GELU ----------------
// D[n_out][pix]; CTA tile 64n x 128m; K chunks of 32 (16 k2 words).
// Warp tile: 32n x 32m (acc 32 regs). 3 CTAs/SM for occupancy.
constexpr int MT  = 128;
constexpr int NT  = 64;
constexpr int KT  = 32;          // k per chunk
constexpr int NCH = K0 / KT;     // 24
constexpr int SXS = 136;         // sX row stride (words), 16 rows/stage
constexpr int SWSH = 40;         // sW row stride (halfs) -> 80B
constexpr int NSTG = 3;
constexpr int SX_STAGE_W = 16 * SXS;          // 2176 words (8704B)
constexpr int SW_STAGE_H = NT * SWSH;         // 2560 halfs (5120B)
constexpr int SMEM_BYTES = NSTG * (SX_STAGE_W * 4 + SW_STAGE_H * 2);  // 41472

__global__ void __launch_bounds__(256, 3) gemm_kernel(
    const float* __restrict__ conv_b,
    const float* __restrict__ bn_scale, const float* __restrict__ bn_bias,
    const float* __restrict__ bn_mean,  const float* __restrict__ bn_var,
    float* __restrict__ out)
{
    extern __shared__ uint32_t smw[];
    uint32_t* sX = smw;                               // [3][16][SXS] words
    __half*   sW = (__half*)(smw + NSTG * SX_STAGE_W);// [3][NT][SWSH] halfs
    __shared__ float s_s[NT], s_t[NT];

    const int tid  = threadIdx.x;
    const int lane = tid & 31;
    const int wid  = tid >> 5;
    const int wn   = wid & 1;           // 2 x 32 n
    const int wp   = wid >> 1;          // 4 x 32 m
    const int n0   = blockIdx.x * NT;
    const int m0   = blockIdx.y * MT;

    if (tid < NT) {
        const int n = n0 + tid;
        const float inv = rsqrtf(bn_var[n] + 1e-5f);
        const float s = inv * bn_scale[n];
        s_s[tid] = s;
        s_t[tid] = (conv_b[n] - bn_mean[n]) * s + bn_bias[n];
    }

    const uint32_t sxB = smem_u32(sX);
    const uint32_t swB = smem_u32(sW);

    auto load_chunk = [&](int ch, int st) {
        const int kc2 = ch * (KT / 2);          // k2 offset
        const uint32_t xb = sxB + (uint32_t)st * SX_STAGE_W * 4;
        const uint32_t wb = swB + (uint32_t)st * SW_STAGE_H * 2;
        // sX: 16 k2-rows x 128 words ; 512 x 16B
#pragma unroll
        for (int i = 0; i < 2; i++) {
            const int idx = tid + 256 * i;
            const int k2  = idx >> 5;           // 0..15
            const int mv  = idx & 31;           // 16B unit (4 m)
            const int m   = m0 + 4 * mv;
            const unsigned b  = (unsigned)m / HW;
            const unsigned hw = (unsigned)m - b * HW;
            const uint32_t* src = g_Xp + ((size_t)b * K2T + kc2 + k2) * HW + hw;
            CP_ASYNC16(xb + (uint32_t)(k2 * SXS + 4 * mv) * 4, src);
        }
        // sW: 64 n-rows x 32 halfs ; 256 x 16B
        {
            const int n   = tid >> 2;           // 0..63
            const int kv  = tid & 3;            // 8-half unit
            const __half* src = g_Wh + (size_t)(n0 + n) * K0 + ch * KT + 8 * kv;
            CP_ASYNC16(wb + (uint32_t)(n * SWSH + 8 * kv) * 2, src);
        }
    };

    float acc[2][4][4];
#pragma unroll
    for (int a = 0; a < 2; a++)
#pragma unroll
        for (int j = 0; j < 4; j++)
#pragma unroll
            for (int q = 0; q < 4; q++) acc[a][j][q] = 0.f;

    // prologue: two chunks in flight
    load_chunk(0, 0);
    CP_COMMIT();
    load_chunk(1, 1);
    CP_COMMIT();

    const int jrow = (lane & 7) + ((lane >> 3) & 1) * 8;
    const int kcol = (lane >> 4) * 8;           // half offset 0 or 8

#pragma unroll 1
    for (int ch = 0; ch < NCH; ch++) {
        if (ch == NCH - 1) { CP_WAIT0(); } else { CP_WAIT1(); }
        __syncthreads();    // stage ch visible; stage (ch-1) fully consumed

        if (ch + 2 < NCH) {
            load_chunk(ch + 2, (ch + 2) % NSTG);
            CP_COMMIT();
        }

        const int st = ch % NSTG;
        const uint32_t xb = sxB + (uint32_t)st * SX_STAGE_W * 4;
        const uint32_t wb = swB + (uint32_t)st * SW_STAGE_H * 2;

#pragma unroll
        for (int ks = 0; ks < 2; ks++) {        // two k16 steps
            const uint32_t bbase = xb + (uint32_t)((ks * 8 + (lane & 3)) * SXS
                                                   + wp * 32 + (lane >> 2)) * 4;
            uint32_t bo[8];
#pragma unroll
            for (int j = 0; j < 4; j++) {
                const uint32_t a0 = bbase + (uint32_t)(j * 8) * 4;
                bo[2 * j]     = lds_u32(a0);
                bo[2 * j + 1] = lds_u32(a0 + (uint32_t)(4 * SXS) * 4);
            }
#pragma unroll
            for (int nf = 0; nf < 2; nf++) {
                uint32_t afr[4];
                const int row = wn * 32 + nf * 16 + jrow;
                ldsm_x4(afr, wb + (uint32_t)(row * SWSH + ks * 16 + kcol) * 2);
#pragma unroll
                for (int j = 0; j < 4; j++)
                    mma_f16(acc[nf][j], afr, bo[2 * j], bo[2 * j + 1]);
            }
        }
    }

    // ---- epilogue: BN + exact GELU ----
#pragma unroll
    for (int nf = 0; nf < 2; nf++) {
#pragma unroll
        for (int half = 0; half < 2; half++) {
            const int ntile = wn * 32 + nf * 16 + (lane >> 2) + half * 8;
            const int n = n0 + ntile;
            const float s = s_s[ntile];
            const float t = s_t[ntile];
#pragma unroll
            for (int j = 0; j < 4; j++) {
                const int m = m0 + wp * 32 + j * 8 + 2 * (lane & 3);
                const unsigned b  = (unsigned)m / HW;
                const unsigned hw = (unsigned)m - b * HW;
                float v0 = acc[nf][j][half * 2 + 0] * s + t;
                float v1 = acc[nf][j][half * 2 + 1] * s + t;
                v0 = 0.5f * v0 * (1.0f + erff(v0 * 0.70710678118654752440f));
                v1 = 0.5f * v1 * (1.0f + erff(v1 * 0.70710678118654752440f));
                *reinterpret_cast<float2*>(
                    out + ((size_t)b * NOUT + n) * HW + hw) = make_float2(v0, v1);
            }
        }
    }
}

// ---------------- launch (single stream, serial) ----------------
extern "C" void kernel_launch(void* const* d_in, const int* in_sizes, int n_in,
                              void* d_out, int out_size) {
    const float* x        = (const float*)d_in[0];
    const float* conv_w   = (const float*)d_in[1];
    const float* conv_b   = (const float*)d_in[2];
    const float* bn_scale = (const float*)d_in[3];
    const float* bn_bias  = (const float*)d_in[4];
    const float* bn_mean  = (const float*)d_in[5];
    const float* bn_var   = (const float*)d_in[6];
    float* out = (float*)d_out;

    cudaFuncSetAttribute(xjpack_kernel,
                         cudaFuncAttributeMaxDynamicSharedMemorySize, XJ_SMEM);
    cudaFuncSetAttribute(gemm_kernel,
                         cudaFuncAttributeMaxDynamicSharedMemorySize, SMEM_BYTES);

    xjpack_kernel<<<XJ_BLOCKS + W_BLOCKS, dim3(64, 7), XJ_SMEM>>>(x, conv_w);
    gemm_kernel<<<dim3(NOUT / NT, M_ / MT), 256, SMEM_BYTES>>>(
        conv_b, bn_scale, bn_bias, bn_mean, bn_var, out);
}

// round 15
// speedup vs baseline: 1.1356x; 1.1356x over previous
#include <cuda_runtime.h>
#include <cuda_fp16.h>
#include <cstdint>

#define DI __device__ __forceinline__

// ---------------- problem constants ----------------
constexpr int B_   = 16;
constexpr int C_   = 384;
constexpr int H_   = 56;
constexpr int W_   = 56;
constexpr int HW   = H_ * W_;          // 3136
constexpr int M_   = B_ * HW;          // 50176 (pixels)
constexpr int K0   = 2 * C_;           // 768
constexpr int K2T  = K0 / 2;           // 384 packed k-pairs
constexpr int NOUT = 384;

// ---------------- device scratch ----------------
__device__ __align__(256) uint32_t g_Xp[(size_t)B_ * K2T * HW];   // 77 MB
__device__ __align__(256) __half   g_Wh[NOUT * K0];               // fp16 W [n][k]

// ---------------- PTX helpers ----------------
DI uint32_t smem_u32(const void* p) {
    uint32_t a;
    asm("{ .reg .u64 t; cvta.to.shared.u64 t, %1; cvt.u32.u64 %0, t; }"
        : "=r"(a) : "l"(p));
    return a;
}

#define CP_ASYNC16(smem, gptr) \
    asm volatile("cp.async.cg.shared.global [%0], [%1], 16;" :: "r"(smem), "l"(gptr))
#define CP_COMMIT() asm volatile("cp.async.commit_group;")
#define CP_WAIT1()  asm volatile("cp.async.wait_group 1;")
#define CP_WAIT0()  asm volatile("cp.async.wait_group 0;")

DI void ldsm_x4(uint32_t* r, uint32_t addr) {
    asm volatile("ldmatrix.sync.aligned.m8n8.x4.shared.b16 {%0,%1,%2,%3}, [%4];"
                 : "=r"(r[0]), "=r"(r[1]), "=r"(r[2]), "=r"(r[3]) : "r"(addr));
}

DI uint32_t lds_u32(uint32_t addr) {
    uint32_t v;
    asm volatile("ld.shared.b32 %0, [%1];" : "=r"(v) : "r"(addr));
    return v;
}

// D[16 n][8 m] += A[16 n][16 k](f16) * B[16 k][8 m](f16), f32 accum
DI void mma_f16(float* d, const uint32_t* a, uint32_t b0, uint32_t b1) {
    asm volatile(
        "mma.sync.aligned.m16n8k16.row.col.f32.f16.f16.f32 "
        "{%0,%1,%2,%3},{%4,%5,%6,%7},{%8,%9},{%0,%1,%2,%3};"
        : "+f"(d[0]), "+f"(d[1]), "+f"(d[2]), "+f"(d[3])
        : "r"(a[0]), "r"(a[1]), "r"(a[2]), "r"(a[3]), "r"(b0), "r"(b1));
}

DI uint32_t pack_h2(float a, float b) {
    __half2 h = __halves2half2(__float2half_rn(a), __float2half_rn(b));
    return *reinterpret_cast<uint32_t*>(&h);
}

DI __half2 u2h(uint32_t u) { return *reinterpret_cast<__half2*>(&u); }
DI uint32_t h2u(__half2 h) { return *reinterpret_cast<uint32_t*>(&h); }

// ---------------- kernel 1: xjpack + fused W conversion ----------------
constexpr int TSTR = 120;
constexpr int XJ_SMEM = 118 * TSTR * 4;             // 56640 B
constexpr int XJ_BLOCKS = B_ * (C_ / 2);            // 3072
constexpr int W_BLOCKS  = 24;
constexpr int W_ELEMS   = NOUT * K0;                // 294912

__global__ void __launch_bounds__(448, 3) xjpack_kernel(
    const float* __restrict__ x, const float* __restrict__ wsrc) {
    extern __shared__ uint32_t t[];

    if (blockIdx.x >= XJ_BLOCKS) {
        const int tid0 = (blockIdx.x - XJ_BLOCKS) * 448
                       + threadIdx.y * 64 + threadIdx.x;
        for (int i = tid0; i < W_ELEMS; i += W_BLOCKS * 448)
            g_Wh[i] = __float2half_rn(wsrc[i]);
        return;
    }

    const int c2 = blockIdx.x % (C_ / 2);
    const int b  = blockIdx.x / (C_ / 2);
    const float* src0 = x + ((size_t)b * C_ + 2 * c2    ) * HW;
    const float* src1 = x + ((size_t)b * C_ + 2 * c2 + 1) * HW;

    const int w  = threadIdx.x;                 // 0..63 (>=56 idle)
    const int ty = threadIdx.y;                 // 0..6
    const int hb = ty * 8;

    if (w < W_) {
#pragma unroll
        for (int j = 0; j < 8; j++)
            t[(31 + hb + j) * TSTR + 31 + w] =
                pack_h2(src0[(hb + j) * W_ + w], src1[(hb + j) * W_ + w]);
    }
    __syncthreads();

    if (w < W_) {
#pragma unroll
        for (int r = ty; r < 31; r += 7) {
            t[r * TSTR + 31 + w]        = t[(r + 56) * TSTR + 31 + w];
            t[(r + 87) * TSTR + 31 + w] = t[(r + 31) * TSTR + 31 + w];
        }
    }
    if (w < 31) {
#pragma unroll
        for (int r = 31 + ty; r < 87; r += 7) {
            t[r * TSTR + w]      = t[r * TSTR + w + 56];
            t[r * TSTR + 87 + w] = t[r * TSTR + 31 + w];
        }
    }
    __syncthreads();

    if (w >= W_) return;

    const uint32_t* bp = &t[(31 + hb) * TSTR + 31 + w];
    uint32_t* dx = g_Xp + ((size_t)b * K2T + c2)       * HW + hb * W_ + w;
    uint32_t* dj = g_Xp + ((size_t)b * K2T + 192 + c2) * HW + hb * W_ + w;

    const __half2 zero = __half2half2(__float2half(0.f));

#pragma unroll 2
    for (int j = 0; j < 8; j++) {
        const uint32_t* p = bp + j * TSTR;
        const uint32_t vw = p[0];
        const __half2 v = u2h(vw);

        __half2 m = __hmin2(u2h(p[-1 * TSTR]),  u2h(p[1 * TSTR]));
        m = __hmin2(m, __hmin2(u2h(p[-3 * TSTR]),  u2h(p[3 * TSTR])));
        m = __hmin2(m, __hmin2(u2h(p[-7 * TSTR]),  u2h(p[7 * TSTR])));
        m = __hmin2(m, __hmin2(u2h(p[-15 * TSTR]), u2h(p[15 * TSTR])));
        m = __hmin2(m, __hmin2(u2h(p[-31 * TSTR]), u2h(p[31 * TSTR])));
        m = __hmin2(m, __hmin2(u2h(p[-1]),  u2h(p[1])));
        m = __hmin2(m, __hmin2(u2h(p[-3]),  u2h(p[3])));
        m = __hmin2(m, __hmin2(u2h(p[-7]),  u2h(p[7])));
        m = __hmin2(m, __hmin2(u2h(p[-15]), u2h(p[15])));
        m = __hmin2(m, __hmin2(u2h(p[-31]), u2h(p[31])));

        dx[j * W_] = vw;
        dj[j * W_] = h2u(__hmax2(__hsub2(v, m), zero));
    }
}

// ---------------- kernel 2: fp16 mma.sync GEMM + BN + GELU ----------------
// D[n_out][pix]; CTA tile 128n x 128m; K chunks of 64 (32 k2 words).
// Warp tile: 64n x 32m (R13 shape). 3-stage pipeline, 12 barriers total.
constexpr int MT  = 128;
constexpr int NT  = 128;
constexpr int KT  = 64;          // k per chunk
constexpr int NCH = K0 / KT;     // 12
constexpr int SXS = 136;         // sX row stride (words), 32 rows/stage
constexpr int SWSH = 72;         // sW row stride (halfs) -> 144B
constexpr int NSTG = 3;
constexpr int SX_STAGE_W = 32 * SXS;          // 4352 words (17408B)
constexpr int SW_STAGE_H = NT * SWSH;         // 9216 halfs (18432B)
constexpr int SMEM_BYTES = NSTG * (SX_STAGE_W * 4 + SW_STAGE_H * 2);  // 107520

__global__ void __launch_bounds__(256, 2) gemm_kernel(
    const float* __restrict__ conv_b,
    const float* __restrict__ bn_scale, const float* __restrict__ bn_bias,
    const float* __restrict__ bn_mean,  const float* __restrict__ bn_var,
    float* __restrict__ out)
{
    extern __shared__ uint32_t smw[];
    uint32_t* sX = smw;                               // [3][32][SXS] words
    __half*   sW = (__half*)(smw + NSTG * SX_STAGE_W);// [3][NT][SWSH] halfs
    __shared__ float s_s[NT], s_t[NT];

    const int tid  = threadIdx.x;
    const int lane = tid & 31;
    const int wid  = tid >> 5;
    const int wn   = wid & 1;           // 2 x 64 n
    const int wp   = wid >> 1;          // 4 x 32 m
    const int n0   = blockIdx.x * NT;
    const int m0   = blockIdx.y * MT;

    if (tid < NT) {
        const int n = n0 + tid;
        const float inv = rsqrtf(bn_var[n] + 1e-5f);
        const float s = inv * bn_scale[n];
        s_s[tid] = s;
        s_t[tid] = (conv_b[n] - bn_mean[n]) * s + bn_bias[n];
    }

    const uint32_t sxB = smem_u32(sX);
    const uint32_t swB = smem_u32(sW);

    auto load_chunk = [&](int ch, int st) {
        const int kc2 = ch * (KT / 2);          // k2 offset (32 per chunk)
        const uint32_t xb = sxB + (uint32_t)st * SX_STAGE_W * 4;
        const uint32_t wb = swB + (uint32_t)st * SW_STAGE_H * 2;
        // sX: 32 k2-rows x 128 words ; 1024 x 16B
#pragma unroll
        for (int i = 0; i < 4; i++) {
            const int idx = tid + 256 * i;
            const int k2  = idx >> 5;           // 0..31
            const int mv  = idx & 31;           // 16B unit (4 m)
            const int m   = m0 + 4 * mv;
            const unsigned b  = (unsigned)m / HW;
            const unsigned hw = (unsigned)m - b * HW;
            const uint32_t* src = g_Xp + ((size_t)b * K2T + kc2 + k2) * HW + hw;
            CP_ASYNC16(xb + (uint32_t)(k2 * SXS + 4 * mv) * 4, src);
        }
        // sW: 128 n-rows x 64 halfs ; 1024 x 16B
#pragma unroll
        for (int i = 0; i < 4; i++) {
            const int idx = tid + 256 * i;
            const int n   = idx >> 3;           // 0..127
            const int kv  = idx & 7;            // 8-half unit
            const __half* src = g_Wh + (size_t)(n0 + n) * K0 + ch * KT + 8 * kv;
            CP_ASYNC16(wb + (uint32_t)(n * SWSH + 8 * kv) * 2, src);
        }
    };

    float acc[4][4][4];
#pragma unroll
    for (int a = 0; a < 4; a++)
#pragma unroll
        for (int j = 0; j < 4; j++)
#pragma unroll
            for (int q = 0; q < 4; q++) acc[a][j][q] = 0.f;

    // prologue: two chunks in flight
    load_chunk(0, 0);
    CP_COMMIT();
    load_chunk(1, 1);
    CP_COMMIT();

    const int jrow = (lane & 7) + ((lane >> 3) & 1) * 8;
    const int kcol = (lane >> 4) * 8;           // half offset 0 or 8

#pragma unroll 1
    for (int ch = 0; ch < NCH; ch++) {
        if (ch == NCH - 1) { CP_WAIT0(); } else { CP_WAIT1(); }
        __syncthreads();    // stage ch visible; stage (ch-1) fully consumed

        if (ch + 2 < NCH) {
            load_chunk(ch + 2, (ch + 2) % NSTG);
            CP_COMMIT();
        }

        const int st = ch % NSTG;
        const uint32_t xb = sxB + (uint32_t)st * SX_STAGE_W * 4;
        const uint32_t wb = swB + (uint32_t)st * SW_STAGE_H * 2;

#pragma unroll
        for (int ks = 0; ks < 4; ks++) {        // four k16 steps
            const uint32_t bbase = xb + (uint32_t)((ks * 8 + (lane & 3)) * SXS
                                                   + wp * 32 + (lane >> 2)) * 4;
            uint32_t bo[8];
#pragma unroll
            for (int j = 0; j < 4; j++) {
                const uint32_t a0 = bbase + (uint32_t)(j * 8) * 4;
                bo[2 * j]     = lds_u32(a0);
                bo[2 * j + 1] = lds_u32(a0 + (uint32_t)(4 * SXS) * 4);
            }
#pragma unroll
            for (int nf = 0; nf < 4; nf++) {
                uint32_t afr[4];
                const int row = wn * 64 + nf * 16 + jrow;
                ldsm_x4(afr, wb + (uint32_t)(row * SWSH + ks * 16 + kcol) * 2);
#pragma unroll
                for (int j = 0; j < 4; j++)
                    mma_f16(acc[nf][j], afr, bo[2 * j], bo[2 * j + 1]);
            }
        }
    }

    // ---- epilogue: BN + exact GELU ----
#pragma unroll
    for (int nf = 0; nf < 4; nf++) {
#pragma unroll
        for (int half = 0; half < 2; half++) {
            const int ntile = wn * 64 + nf * 16 + (lane >> 2) + half * 8;
            const int n = n0 + ntile;
            const float s = s_s[ntile];
            const float t = s_t[ntile];
#pragma unroll
            for (int j = 0; j < 4; j++) {
                const int m = m0 + wp * 32 + j * 8 + 2 * (lane & 3);
                const unsigned b  = (unsigned)m / HW;
                const unsigned hw = (unsigned)m - b * HW;
                float v0 = acc[nf][j][half * 2 + 0] * s + t;
                float v1 = acc[nf][j][half * 2 + 1] * s + t;
                v0 = 0.5f * v0 * (1.0f + erff(v0 * 0.70710678118654752440f));
                v1 = 0.5f * v1 * (1.0f + erff(v1 * 0.70710678118654752440f));
                *reinterpret_cast<float2*>(
                    out + ((size_t)b * NOUT + n) * HW + hw) = make_float2(v0, v1);
            }
        }
    }
}

// ---------------- launch (single stream, serial) ----------------
extern "C" void kernel_launch(void* const* d_in, const int* in_sizes, int n_in,
                              void* d_out, int out_size) {
    const float* x        = (const float*)d_in[0];
    const float* conv_w   = (const float*)d_in[1];
    const float* conv_b   = (const float*)d_in[2];
    const float* bn_scale = (const float*)d_in[3];
    const float* bn_bias  = (const float*)d_in[4];
    const float* bn_mean  = (const float*)d_in[5];
    const float* bn_var   = (const float*)d_in[6];
    float* out = (float*)d_out;

    cudaFuncSetAttribute(xjpack_kernel,
                         cudaFuncAttributeMaxDynamicSharedMemorySize, XJ_SMEM);
    cudaFuncSetAttribute(gemm_kernel,
                         cudaFuncAttributeMaxDynamicSharedMemorySize, SMEM_BYTES);

    xjpack_kernel<<<XJ_BLOCKS + W_BLOCKS, dim3(64, 7), XJ_SMEM>>>(x, conv_w);
    gemm_kernel<<<dim3(NOUT / NT, M_ / MT), 256, SMEM_BYTES>>>(
        conv_b, bn_scale, bn_bias, bn_mean, bn_var, out);
}